// round 11
// baseline (speedup 1.0000x reference)
#include <cuda_runtime.h>
#include <float.h>
#include <math.h>
#include <stdint.h>

// Problem constants
#define NPTS 12288
#define DIM 64
#define KNN 16
#define KP  20                    // padded candidate list depth
#define EPS 1e-5f
#define DIAG_BIAS 1e6f

// Tiling: 256 threads (8 warps x m16), BI=128 rows, BJ=64 cols per tile
#define THREADS 256
#define BI 128
#define BJ 64
#define NSEG 3
#define SEGJ (NPTS / NSEG)        // 4096
#define NTILES (SEGJ / BJ)        // 64
#define NROWBLK (NPTS / BI)       // 96
#define NCAND (NSEG * KP)         // 60 candidates per row

// smem layout (floats). sj holds hi-only j-tiles, permuted k order: [col][64].
// SJ_STRIDE = 72 (== 8 mod 32) -> B-fragment LDS.64 lane granules 4g+t are
// distinct within each 16-lane phase: conflict-free.
#define SJ_STRIDE 72
#define SJ_BUF (BJ * SJ_STRIDE)                      // 4608
#define SSQJ_OFF (2 * SJ_BUF)                        // 9216
#define LV_OFF (SSQJ_OFF + 2 * BJ)                   // 9344
#define LI_OFF (LV_OFF + THREADS * 2 * KP)           // 19584
#define SMEM_FLOATS (LI_OFF + (THREADS * 2 * KP) / 2) // 24704
#define SMEM_BYTES (SMEM_FLOATS * 4)                 // 98816

// Scratch (no allocations -> device globals)
__device__ float g_hi[NPTS * DIM];   // tf32-rounded coords, permuted k order
__device__ float g_sq[NPTS];
__device__ float g_colsum[DIM];
__device__ float g_sigma_inv;
__device__ float g_vals[NPTS * NSEG * KP];
__device__ int   g_idx [NPTS * NSEG * KP];

typedef unsigned long long u64;

__device__ __forceinline__ uint32_t sptr(const void* p) {
    return (uint32_t)__cvta_generic_to_shared(p);
}
__device__ __forceinline__ void cp_async16(uint32_t dst, const void* src) {
    asm volatile("cp.async.cg.shared.global [%0], [%1], 16;" :: "r"(dst), "l"(src));
}
__device__ __forceinline__ void cp_async4(uint32_t dst, const void* src) {
    asm volatile("cp.async.ca.shared.global [%0], [%1], 4;" :: "r"(dst), "l"(src));
}
#define CP_COMMIT() asm volatile("cp.async.commit_group;")
#define CP_WAIT0()  asm volatile("cp.async.wait_group 0;")

// packed fp32x2 fma (R2's exact-scoring instruction)
__device__ __forceinline__ u64 ffma2(u64 a, u64 b, u64 c) {
    u64 d;
    asm("fma.rn.f32x2 %0, %1, %2, %3;" : "=l"(d) : "l"(a), "l"(b), "l"(c));
    return d;
}
__device__ __forceinline__ float pairsum(u64 a) {
    float lo = __uint_as_float((unsigned)(a & 0xffffffffull));
    float hi = __uint_as_float((unsigned)(a >> 32));
    return lo + hi;
}

// m16n8k8 tf32 mma: D = A*B + D (row-major A, col-major B), fp32 accum
__device__ __forceinline__ void mma_tf32(float (&c)[4], const uint32_t* a,
                                         uint32_t b0, uint32_t b1) {
    asm volatile(
        "mma.sync.aligned.m16n8k8.row.col.f32.tf32.tf32.f32 "
        "{%0,%1,%2,%3}, {%4,%5,%6,%7}, {%8,%9}, {%0,%1,%2,%3};"
        : "+f"(c[0]), "+f"(c[1]), "+f"(c[2]), "+f"(c[3])
        : "r"(a[0]), "r"(a[1]), "r"(a[2]), "r"(a[3]), "r"(b0), "r"(b1));
}

// ---------------------------------------------------------------------------
// Prologue: tf32-round coords into g_hi with permuted k order:
// within each 8-k chunk kc, k = kc*8 + r is stored at kc*8 + (r%4)*2 + (r/4),
// so the fragment pair (k=t, k=t+4) is a contiguous float2.
// ---------------------------------------------------------------------------
__global__ void hi_kernel(const float* __restrict__ coords) {
    int i = blockIdx.x * 256 + threadIdx.x;   // 0 .. NPTS*DIM-1
    int row = i >> 6, k = i & 63;
    int kc = k >> 3, r = k & 7;
    int pos = kc * 8 + (r & 3) * 2 + (r >> 2);
    float x = coords[i];
    uint32_t h;
    asm("cvt.rna.tf32.f32 %0, %1;" : "=r"(h) : "f"(x));
    g_hi[row * DIM + pos] = __uint_as_float(h);
}

// ---------------------------------------------------------------------------
__global__ void sq_kernel(const float* __restrict__ coords) {
    int row = blockIdx.x * 256 + threadIdx.x;
    const float4* p = (const float4*)(coords + (size_t)row * DIM);
    float s = 0.f;
#pragma unroll
    for (int t = 0; t < DIM / 4; ++t) {
        float4 v = p[t];
        s += v.x * v.x + v.y * v.y + v.z * v.z + v.w * v.w;
    }
    g_sq[row] = s;
}

__global__ void colsum_kernel(const float* __restrict__ coords) {
    __shared__ float red[256];
    int d = blockIdx.x;
    float s = 0.f;
    for (int r = threadIdx.x; r < NPTS; r += 256)
        s += coords[(size_t)r * DIM + d];
    red[threadIdx.x] = s;
    __syncthreads();
    for (int off = 128; off > 0; off >>= 1) {
        if (threadIdx.x < off) red[threadIdx.x] += red[threadIdx.x + off];
        __syncthreads();
    }
    if (threadIdx.x == 0) g_colsum[d] = red[0];
}

__global__ void sigma_kernel() {
    __shared__ double red[256];
    double s = 0.0;
    for (int r = threadIdx.x; r < NPTS; r += 256)
        s += (double)g_sq[r];
    red[threadIdx.x] = s;
    __syncthreads();
    for (int off = 128; off > 0; off >>= 1) {
        if (threadIdx.x < off) red[threadIdx.x] += red[threadIdx.x + off];
        __syncthreads();
    }
    if (threadIdx.x == 0) {
        double sumsq = red[0];
        double nrm2 = 0.0;
        for (int d = 0; d < DIM; ++d) {
            double c = (double)g_colsum[d];
            nrm2 += c * c;
        }
        const double Nd = (double)NPTS;
        double total = 2.0 * Nd * sumsq - 2.0 * nrm2
                     + Nd * Nd * (double)EPS + Nd * (double)DIAG_BIAS;
        double sigma2 = total / (Nd * Nd);
        g_sigma_inv = (float)(1.0 / (sigma2 + (double)EPS));
    }
}

// lexicographic (value, index) sorted insert (R9-passing semantics)
__device__ __forceinline__ void topk_insert_tie(float (&vals)[KNN],
                                                int (&idx)[KNN],
                                                float v, int id) {
#pragma unroll
    for (int t = 0; t < KNN; ++t) {
        bool lt = (v < vals[t]) || (v == vals[t] && id < idx[t]);
        if (lt) {
            float tv = vals[t]; vals[t] = v; v = tv;
            int   ti = idx[t];  idx[t]  = id; id = ti;
        }
    }
}

// smem sorted insert (KP-deep); caller guarantees v < lv[KP-1] (rare path)
__device__ __forceinline__ void smem_insert(float* __restrict__ lv,
                                            unsigned short* __restrict__ li,
                                            float v, int id, float& thr) {
    int t = KP - 1;
    while (t > 0) {
        float p = lv[t - 1];
        if (p <= v) break;
        lv[t] = p;
        li[t] = li[t - 1];
        --t;
    }
    lv[t] = v;
    li[t] = (unsigned short)id;
    thr = lv[KP - 1];
}

// ---------------------------------------------------------------------------
// Stage one 64-row hi-only j-tile (256B per row, direct copy of g_hi rows).
// ---------------------------------------------------------------------------
__device__ __forceinline__ void issue_jtile(int jbase, float* sjb,
                                            float* ssqjb, int tid) {
    int r = tid >> 2;        // 0..63 tile row
    int c4 = tid & 3;
    const float* src = g_hi + (size_t)(jbase + r) * DIM;
    float* dst = sjb + r * SJ_STRIDE;
#pragma unroll
    for (int m = 0; m < 4; ++m) {
        int ch = c4 + m * 4;  // 16B chunk 0..15
        cp_async16(sptr(dst + ch * 4), src + ch * 4);
    }
    if (tid < BJ) cp_async4(sptr(ssqjb + tid), &g_sq[jbase + tid]);
}

// ---------------------------------------------------------------------------
// Kernel B: single-tf32 tensor-core distance tiles + streaming top-KP.
// Warp-uniform ballot skips the divergent insert path in the common case.
// ---------------------------------------------------------------------------
__global__ void __launch_bounds__(THREADS, 2)
knn_mma_kernel() {
    extern __shared__ float smem[];
    float* sj   = smem;
    float* ssqj = smem + SSQJ_OFF;

    const int tid = threadIdx.x;
    const int w = tid >> 5, l = tid & 31;
    const int g = l >> 2, t = l & 3;
    const int row0 = blockIdx.x * BI;
    const int jseg = blockIdx.y * SEGJ;
    const int rowA0 = row0 + w * 16 + g;
    const int rowA1 = rowA0 + 8;

    float*          lv0 = smem + LV_OFF + (tid * 2 + 0) * KP;
    float*          lv1 = smem + LV_OFF + (tid * 2 + 1) * KP;
    unsigned short* li0 = (unsigned short*)(smem + LI_OFF) + (tid * 2 + 0) * KP;
    unsigned short* li1 = (unsigned short*)(smem + LI_OFF) + (tid * 2 + 1) * KP;
    float thr0 = FLT_MAX, thr1 = FLT_MAX;
#pragma unroll
    for (int k = 0; k < KP; ++k) {
        lv0[k] = FLT_MAX; lv1[k] = FLT_MAX; li0[k] = 0; li1[k] = 0;
    }

    // A fragments (persistent, hi only): permuted layout gives (k=t, k=t+4)
    // as one float2 -> (a0,a2) for row0 and (a1,a3) for row1 per chunk.
    uint32_t ah[32];
#pragma unroll
    for (int kc = 0; kc < 8; ++kc) {
        float2 p0 = *(const float2*)&g_hi[(size_t)rowA0 * DIM + kc * 8 + 2 * t];
        float2 p1 = *(const float2*)&g_hi[(size_t)rowA1 * DIM + kc * 8 + 2 * t];
        ah[kc * 4 + 0] = __float_as_uint(p0.x);
        ah[kc * 4 + 1] = __float_as_uint(p1.x);
        ah[kc * 4 + 2] = __float_as_uint(p0.y);
        ah[kc * 4 + 3] = __float_as_uint(p1.y);
    }
    const float sqi0 = g_sq[rowA0];
    const float sqi1 = g_sq[rowA1];

    issue_jtile(jseg, sj, ssqj, tid);
    CP_COMMIT();

    int buf = 0;
    for (int tile = 0; tile < NTILES; ++tile) {
        const int jbase = jseg + tile * BJ;
        CP_WAIT0();
        __syncthreads();

        if (tile + 1 < NTILES) {
            issue_jtile(jbase + BJ, sj + (buf ^ 1) * SJ_BUF,
                        ssqj + (buf ^ 1) * BJ, tid);
            CP_COMMIT();
        }

        const float* sjb = sj + buf * SJ_BUF;
#pragma unroll
        for (int nt2 = 0; nt2 < 4; ++nt2) {
            float c0[4] = {0.f, 0.f, 0.f, 0.f};
            float c1[4] = {0.f, 0.f, 0.f, 0.f};
            const float* b0p = sjb + (nt2 * 16 + g) * SJ_STRIDE + 2 * t;
            const float* b1p = sjb + (nt2 * 16 + 8 + g) * SJ_STRIDE + 2 * t;
#pragma unroll
            for (int kc = 0; kc < 8; ++kc) {
                float2 b0 = *(const float2*)(b0p + kc * 8);  // (k=t, k=t+4)
                float2 b1 = *(const float2*)(b1p + kc * 8);
                mma_tf32(c0, ah + kc * 4, __float_as_uint(b0.x), __float_as_uint(b0.y));
                mma_tf32(c1, ah + kc * 4, __float_as_uint(b1.x), __float_as_uint(b1.y));
            }
#pragma unroll
            for (int h = 0; h < 2; ++h) {
                const float* c = h ? c1 : c0;
                const int nt = nt2 * 2 + h;
                const int colb = nt * 8 + 2 * t;
                const float sqj0 = ssqj[buf * BJ + colb];
                const float sqj1 = ssqj[buf * BJ + colb + 1];
                const int col0 = jbase + colb, col1 = col0 + 1;
                float d0 = fmaf(-2.f, c[0], sqi0 + sqj0 + EPS);
                float d1 = fmaf(-2.f, c[1], sqi0 + sqj1 + EPS);
                float d2 = fmaf(-2.f, c[2], sqi1 + sqj0 + EPS);
                float d3 = fmaf(-2.f, c[3], sqi1 + sqj1 + EPS);
                if (rowA0 == col0) d0 += DIAG_BIAS;
                if (rowA0 == col1) d1 += DIAG_BIAS;
                if (rowA1 == col0) d2 += DIAG_BIAS;
                if (rowA1 == col1) d3 += DIAG_BIAS;
                // warp-uniform skip: common case is no lane needs an insert
                bool need = (fminf(d0, d1) < thr0) | (fminf(d2, d3) < thr1);
                if (__ballot_sync(0xffffffffu, need)) {
                    if (d0 < thr0) smem_insert(lv0, li0, d0, col0, thr0);
                    if (d1 < thr0) smem_insert(lv0, li0, d1, col1, thr0);
                    if (d2 < thr1) smem_insert(lv1, li1, d2, col0, thr1);
                    if (d3 < thr1) smem_insert(lv1, li1, d3, col1, thr1);
                }
            }
        }
        buf ^= 1;
    }

    // ---- merge the 4 t-lane lists per row, emit per-segment candidates ----
    __syncthreads();
    if (t == 0) {
#pragma unroll
        for (int p = 1; p < 4; ++p) {
            const float*          pv = lv0 + p * 2 * KP;
            const unsigned short* pi = li0 + p * 2 * KP;
#pragma unroll
            for (int k = 0; k < KP; ++k) {
                float c = pv[k];
                if (c < thr0) smem_insert(lv0, li0, c, (int)pi[k], thr0);
            }
            const float*          qv = lv1 + p * 2 * KP;
            const unsigned short* qi = li1 + p * 2 * KP;
#pragma unroll
            for (int k = 0; k < KP; ++k) {
                float c = qv[k];
                if (c < thr1) smem_insert(lv1, li1, c, (int)qi[k], thr1);
            }
        }
        const size_t o0 = ((size_t)rowA0 * NSEG + blockIdx.y) * KP;
        const size_t o1 = ((size_t)rowA1 * NSEG + blockIdx.y) * KP;
#pragma unroll
        for (int k = 0; k < KP; ++k) {
            g_vals[o0 + k] = lv0[k];
            g_idx [o0 + k] = (int)li0[k];
            g_vals[o1 + k] = lv1[k];
            g_idx [o1 + k] = (int)li1[k];
        }
    }
}

// ---------------------------------------------------------------------------
// Kernel C: rescore the 60 candidates per row with R2's EXACT arithmetic
// (ffma2 even/odd-pair chain, pairsum lo+hi, d = fma(-2, dot, (sqi+EPS)+sqj)),
// lexicographic tie-break top-16, Laplacian. (Unchanged from passing R9.)
// ---------------------------------------------------------------------------
__global__ void __launch_bounds__(128)
rescore_lap_kernel(const float* __restrict__ coords,
                   const float* __restrict__ potential,
                   float* __restrict__ out) {
    const int row = blockIdx.x * 128 + threadIdx.x;

    u64 xi2[DIM / 2];
    {
        const u64* p = (const u64*)(coords + (size_t)row * DIM);
#pragma unroll
        for (int s = 0; s < DIM / 2; ++s) xi2[s] = p[s];
    }
    const float sqi = g_sq[row];
    const float base_i = sqi + EPS;

    float vals[KNN];
    int   idx[KNN];
#pragma unroll
    for (int t = 0; t < KNN; ++t) { vals[t] = FLT_MAX; idx[t] = 0x7fffffff; }

    const size_t cbase = (size_t)row * NCAND;
#pragma unroll 2
    for (int c = 0; c < NCAND; ++c) {
        const int j = g_idx[cbase + c];
        const ulonglong2* xj = (const ulonglong2*)(coords + (size_t)j * DIM);
        u64 acc = 0ull;
#pragma unroll
        for (int s = 0; s < DIM / 2; s += 2) {
            ulonglong2 v = xj[s >> 1];
            acc = ffma2(xi2[s], v.x, acc);
            acc = ffma2(xi2[s + 1], v.y, acc);
        }
        const float dot = pairsum(acc);
        const float d = fmaf(-2.f, dot, base_i + g_sq[j]);
        if (d < vals[KNN - 1] || (d == vals[KNN - 1] && j < idx[KNN - 1]))
            topk_insert_tie(vals, idx, d, j);
    }

    const float inv = g_sigma_inv;
    const float vi  = potential[row];
    float lap = 0.f;
#pragma unroll
    for (int t = 0; t < KNN; ++t) {
        float w = expf(-vals[t] * inv);
        lap += w * (potential[idx[t]] - vi);
    }
    out[row] = lap;
}

// ---------------------------------------------------------------------------
extern "C" void kernel_launch(void* const* d_in, const int* in_sizes, int n_in,
                              void* d_out, int out_size) {
    const float* coords    = (const float*)d_in[0];
    const float* potential = (const float*)d_in[1];
    float* out = (float*)d_out;

    cudaFuncSetAttribute(knn_mma_kernel,
                         cudaFuncAttributeMaxDynamicSharedMemorySize,
                         SMEM_BYTES);

    // Launch order arranged so knn_mma_kernel is the 4th launch -> it is the
    // kernel ncu captures (-s/-c window), finally giving us its profile.
    hi_kernel<<<NPTS * DIM / 256, 256>>>(coords);     // 1
    sq_kernel<<<NPTS / 256, 256>>>(coords);           // 2
    colsum_kernel<<<DIM, 256>>>(coords);              // 3
    dim3 grid(NROWBLK, NSEG);
    knn_mma_kernel<<<grid, THREADS, SMEM_BYTES>>>();  // 4  <- profiled
    sigma_kernel<<<1, 256>>>();                       // 5 (only rescore needs it)
    rescore_lap_kernel<<<NPTS / 128, 128>>>(coords, potential, out);  // 6
}

// round 12
// speedup vs baseline: 3.5869x; 3.5869x over previous
#include <cuda_runtime.h>
#include <float.h>
#include <math.h>
#include <stdint.h>

// Problem constants
#define NPTS 12288
#define DIM 64
#define KNN 16
#define EPS 1e-5f
#define DIAG_BIAS 1e6f

// Tiling: 256 threads (8 warps x m16), BI=128 rows, BJ=64 cols per tile
#define THREADS 256
#define BI 128
#define BJ 64
#define NSEG 3
#define SEGJ (NPTS / NSEG)        // 4096
#define NTILES (SEGJ / BJ)        // 64
#define NROWBLK (NPTS / BI)       // 96
#define CPSEG 64                  // candidates emitted per (row, segment)
#define NCAND (NSEG * CPSEG)      // 192 candidates per row

// smem layout (floats). sj holds hi-only j-tiles, permuted k order: [col][64].
// SJ_STRIDE = 72 (== 8 mod 32) -> B-fragment LDS.64 conflict-free.
#define SJ_STRIDE 72
#define SJ_BUF (BJ * SJ_STRIDE)                      // 4608
#define SSQJ_OFF (2 * SJ_BUF)                        // 9216
#define SMEM_FLOATS (SSQJ_OFF + 2 * BJ)              // 9344
#define SMEM_BYTES (SMEM_FLOATS * 4)                 // 37376

// Scratch (no allocations -> device globals)
__device__ float g_hi[NPTS * DIM];   // tf32-rounded coords, permuted k order
__device__ float g_sq[NPTS];
__device__ float g_colsum[DIM];
__device__ float g_sigma_inv;
__device__ int   g_cand[NPTS * NCAND];

typedef unsigned long long u64;

__device__ __forceinline__ uint32_t sptr(const void* p) {
    return (uint32_t)__cvta_generic_to_shared(p);
}
__device__ __forceinline__ void cp_async16(uint32_t dst, const void* src) {
    asm volatile("cp.async.cg.shared.global [%0], [%1], 16;" :: "r"(dst), "l"(src));
}
__device__ __forceinline__ void cp_async4(uint32_t dst, const void* src) {
    asm volatile("cp.async.ca.shared.global [%0], [%1], 4;" :: "r"(dst), "l"(src));
}
#define CP_COMMIT() asm volatile("cp.async.commit_group;")
#define CP_WAIT0()  asm volatile("cp.async.wait_group 0;")

// packed fp32x2 fma (R2's exact-scoring instruction)
__device__ __forceinline__ u64 ffma2(u64 a, u64 b, u64 c) {
    u64 d;
    asm("fma.rn.f32x2 %0, %1, %2, %3;" : "=l"(d) : "l"(a), "l"(b), "l"(c));
    return d;
}
__device__ __forceinline__ float pairsum(u64 a) {
    float lo = __uint_as_float((unsigned)(a & 0xffffffffull));
    float hi = __uint_as_float((unsigned)(a >> 32));
    return lo + hi;
}

// m16n8k8 tf32 mma: D = A*B + D (row-major A, col-major B), fp32 accum
__device__ __forceinline__ void mma_tf32(float (&c)[4], const uint32_t* a,
                                         uint32_t b0, uint32_t b1) {
    asm volatile(
        "mma.sync.aligned.m16n8k8.row.col.f32.tf32.tf32.f32 "
        "{%0,%1,%2,%3}, {%4,%5,%6,%7}, {%8,%9}, {%0,%1,%2,%3};"
        : "+f"(c[0]), "+f"(c[1]), "+f"(c[2]), "+f"(c[3])
        : "r"(a[0]), "r"(a[1]), "r"(a[2]), "r"(a[3]), "r"(b0), "r"(b1));
}

// ---------------------------------------------------------------------------
// Prologue: tf32-round coords into g_hi with permuted k order (fragment pairs
// (k=t, k=t+4) contiguous).
// ---------------------------------------------------------------------------
__global__ void hi_kernel(const float* __restrict__ coords) {
    int i = blockIdx.x * 256 + threadIdx.x;   // 0 .. NPTS*DIM-1
    int row = i >> 6, k = i & 63;
    int kc = k >> 3, r = k & 7;
    int pos = kc * 8 + (r & 3) * 2 + (r >> 2);
    float x = coords[i];
    uint32_t h;
    asm("cvt.rna.tf32.f32 %0, %1;" : "=r"(h) : "f"(x));
    g_hi[row * DIM + pos] = __uint_as_float(h);
}

// ---------------------------------------------------------------------------
__global__ void sq_kernel(const float* __restrict__ coords) {
    int row = blockIdx.x * 256 + threadIdx.x;
    const float4* p = (const float4*)(coords + (size_t)row * DIM);
    float s = 0.f;
#pragma unroll
    for (int t = 0; t < DIM / 4; ++t) {
        float4 v = p[t];
        s += v.x * v.x + v.y * v.y + v.z * v.z + v.w * v.w;
    }
    g_sq[row] = s;
}

__global__ void colsum_kernel(const float* __restrict__ coords) {
    __shared__ float red[256];
    int d = blockIdx.x;
    float s = 0.f;
    for (int r = threadIdx.x; r < NPTS; r += 256)
        s += coords[(size_t)r * DIM + d];
    red[threadIdx.x] = s;
    __syncthreads();
    for (int off = 128; off > 0; off >>= 1) {
        if (threadIdx.x < off) red[threadIdx.x] += red[threadIdx.x + off];
        __syncthreads();
    }
    if (threadIdx.x == 0) g_colsum[d] = red[0];
}

__global__ void sigma_kernel() {
    __shared__ double red[256];
    double s = 0.0;
    for (int r = threadIdx.x; r < NPTS; r += 256)
        s += (double)g_sq[r];
    red[threadIdx.x] = s;
    __syncthreads();
    for (int off = 128; off > 0; off >>= 1) {
        if (threadIdx.x < off) red[threadIdx.x] += red[threadIdx.x + off];
        __syncthreads();
    }
    if (threadIdx.x == 0) {
        double sumsq = red[0];
        double nrm2 = 0.0;
        for (int d = 0; d < DIM; ++d) {
            double c = (double)g_colsum[d];
            nrm2 += c * c;
        }
        const double Nd = (double)NPTS;
        double total = 2.0 * Nd * sumsq - 2.0 * nrm2
                     + Nd * Nd * (double)EPS + Nd * (double)DIAG_BIAS;
        double sigma2 = total / (Nd * Nd);
        g_sigma_inv = (float)(1.0 / (sigma2 + (double)EPS));
    }
}

// lexicographic (value, index) sorted insert (R9-passing semantics)
__device__ __forceinline__ void topk_insert_tie(float (&vals)[KNN],
                                                int (&idx)[KNN],
                                                float v, int id) {
#pragma unroll
    for (int t = 0; t < KNN; ++t) {
        bool lt = (v < vals[t]) || (v == vals[t] && id < idx[t]);
        if (lt) {
            float tv = vals[t]; vals[t] = v; v = tv;
            int   ti = idx[t];  idx[t]  = id; id = ti;
        }
    }
}

// register key-list insert: sorted ascending, 16 deep, pure min/max chain.
// Caller guarantees k < ks[15].
__device__ __forceinline__ void key_insert(uint32_t (&ks)[16], uint32_t k) {
#pragma unroll
    for (int t = 0; t < 16; ++t) {
        uint32_t cur = ks[t];
        uint32_t lo = (k < cur) ? k : cur;
        uint32_t hi = (k < cur) ? cur : k;
        ks[t] = lo;
        k = hi;
    }
}

// ---------------------------------------------------------------------------
// Stage one 64-row hi-only j-tile (256B per row, direct copy of g_hi rows).
// ---------------------------------------------------------------------------
__device__ __forceinline__ void issue_jtile(int jbase, float* sjb,
                                            float* ssqjb, int tid) {
    int r = tid >> 2;        // 0..63 tile row
    int c4 = tid & 3;
    const float* src = g_hi + (size_t)(jbase + r) * DIM;
    float* dst = sjb + r * SJ_STRIDE;
#pragma unroll
    for (int m = 0; m < 4; ++m) {
        int ch = c4 + m * 4;  // 16B chunk 0..15
        cp_async16(sptr(dst + ch * 4), src + ch * 4);
    }
    if (tid < BJ) cp_async4(sptr(ssqjb + tid), &g_sq[jbase + tid]);
}

// ---------------------------------------------------------------------------
// Kernel B: single-tf32 tensor-core distance tiles + register-packed top-16.
// key = (dist_bits & ~0xFFF) | col_in_seg  -> one uint per candidate,
// insert = 16x min/max chain in registers. No smem lists, no ballot.
// ---------------------------------------------------------------------------
__global__ void __launch_bounds__(THREADS, 2)
knn_mma_kernel() {
    extern __shared__ float smem[];
    float* sj   = smem;
    float* ssqj = smem + SSQJ_OFF;

    const int tid = threadIdx.x;
    const int w = tid >> 5, l = tid & 31;
    const int g = l >> 2, t = l & 3;
    const int row0 = blockIdx.x * BI;
    const int jseg = blockIdx.y * SEGJ;
    const int rowA0 = row0 + w * 16 + g;
    const int rowA1 = rowA0 + 8;

    uint32_t key0[16], key1[16];
#pragma unroll
    for (int k = 0; k < 16; ++k) { key0[k] = 0xFFFFFFFFu; key1[k] = 0xFFFFFFFFu; }

    // A fragments (persistent, hi only)
    uint32_t ah[32];
#pragma unroll
    for (int kc = 0; kc < 8; ++kc) {
        float2 p0 = *(const float2*)&g_hi[(size_t)rowA0 * DIM + kc * 8 + 2 * t];
        float2 p1 = *(const float2*)&g_hi[(size_t)rowA1 * DIM + kc * 8 + 2 * t];
        ah[kc * 4 + 0] = __float_as_uint(p0.x);
        ah[kc * 4 + 1] = __float_as_uint(p1.x);
        ah[kc * 4 + 2] = __float_as_uint(p0.y);
        ah[kc * 4 + 3] = __float_as_uint(p1.y);
    }
    const float sqi0e = g_sq[rowA0] + EPS;
    const float sqi1e = g_sq[rowA1] + EPS;

    issue_jtile(jseg, sj, ssqj, tid);
    CP_COMMIT();

    int buf = 0;
    for (int tile = 0; tile < NTILES; ++tile) {
        const int jbase = jseg + tile * BJ;
        CP_WAIT0();
        __syncthreads();

        if (tile + 1 < NTILES) {
            issue_jtile(jbase + BJ, sj + (buf ^ 1) * SJ_BUF,
                        ssqj + (buf ^ 1) * BJ, tid);
            CP_COMMIT();
        }

        const float* sjb = sj + buf * SJ_BUF;
#pragma unroll
        for (int nt2 = 0; nt2 < 4; ++nt2) {
            float c0[4] = {0.f, 0.f, 0.f, 0.f};
            float c1[4] = {0.f, 0.f, 0.f, 0.f};
            const float* b0p = sjb + (nt2 * 16 + g) * SJ_STRIDE + 2 * t;
            const float* b1p = sjb + (nt2 * 16 + 8 + g) * SJ_STRIDE + 2 * t;
#pragma unroll
            for (int kc = 0; kc < 8; ++kc) {
                float2 b0 = *(const float2*)(b0p + kc * 8);  // (k=t, k=t+4)
                float2 b1 = *(const float2*)(b1p + kc * 8);
                mma_tf32(c0, ah + kc * 4, __float_as_uint(b0.x), __float_as_uint(b0.y));
                mma_tf32(c1, ah + kc * 4, __float_as_uint(b1.x), __float_as_uint(b1.y));
            }
#pragma unroll
            for (int h = 0; h < 2; ++h) {
                const float* c = h ? c1 : c0;
                const int nt = nt2 * 2 + h;
                const int colb = nt * 8 + 2 * t;
                const float sqj0 = ssqj[buf * BJ + colb];
                const float sqj1 = ssqj[buf * BJ + colb + 1];
                const int col0 = jbase + colb, col1 = col0 + 1;
                const uint32_t cin0 = (uint32_t)(tile * BJ + colb);
                float d0 = fmaf(-2.f, c[0], sqi0e + sqj0);
                float d1 = fmaf(-2.f, c[1], sqi0e + sqj1);
                float d2 = fmaf(-2.f, c[2], sqi1e + sqj0);
                float d3 = fmaf(-2.f, c[3], sqi1e + sqj1);
                if (rowA0 == col0) d0 += DIAG_BIAS;
                if (rowA0 == col1) d1 += DIAG_BIAS;
                if (rowA1 == col0) d2 += DIAG_BIAS;
                if (rowA1 == col1) d3 += DIAG_BIAS;
                uint32_t k0 = (__float_as_uint(d0) & 0xFFFFF000u) | cin0;
                uint32_t k1 = (__float_as_uint(d1) & 0xFFFFF000u) | (cin0 + 1);
                uint32_t k2 = (__float_as_uint(d2) & 0xFFFFF000u) | cin0;
                uint32_t k3 = (__float_as_uint(d3) & 0xFFFFF000u) | (cin0 + 1);
                if (k0 < key0[15]) key_insert(key0, k0);
                if (k1 < key0[15]) key_insert(key0, k1);
                if (k2 < key1[15]) key_insert(key1, k2);
                if (k3 < key1[15]) key_insert(key1, k3);
            }
        }
        buf ^= 1;
    }

    // ---- emit candidate indices (no merge: 4 lanes x 16 per row-segment) ----
    {
        const size_t o0 = ((size_t)rowA0 * NSEG + blockIdx.y) * CPSEG + t * 16;
        const size_t o1 = ((size_t)rowA1 * NSEG + blockIdx.y) * CPSEG + t * 16;
#pragma unroll
        for (int k = 0; k < 16; ++k) {
            g_cand[o0 + k] = jseg + (int)(key0[k] & 0xFFFu);
            g_cand[o1 + k] = jseg + (int)(key1[k] & 0xFFFu);
        }
    }
}

// ---------------------------------------------------------------------------
// Kernel C: rescore the 192 candidates per row with R2's EXACT arithmetic
// (ffma2 even/odd-pair chain, pairsum lo+hi, d = fma(-2, dot, (sqi+EPS)+sqj)),
// lexicographic tie-break top-16, Laplacian. (Same semantics as passing R9.)
// ---------------------------------------------------------------------------
__global__ void __launch_bounds__(128)
rescore_lap_kernel(const float* __restrict__ coords,
                   const float* __restrict__ potential,
                   float* __restrict__ out) {
    const int row = blockIdx.x * 128 + threadIdx.x;

    u64 xi2[DIM / 2];
    {
        const u64* p = (const u64*)(coords + (size_t)row * DIM);
#pragma unroll
        for (int s = 0; s < DIM / 2; ++s) xi2[s] = p[s];
    }
    const float base_i = g_sq[row] + EPS;

    float vals[KNN];
    int   idx[KNN];
#pragma unroll
    for (int t = 0; t < KNN; ++t) { vals[t] = FLT_MAX; idx[t] = 0x7fffffff; }

    const size_t cbase = (size_t)row * NCAND;
#pragma unroll 2
    for (int c = 0; c < NCAND; ++c) {
        const int j = g_cand[cbase + c];
        const ulonglong2* xj = (const ulonglong2*)(coords + (size_t)j * DIM);
        u64 acc = 0ull;
#pragma unroll
        for (int s = 0; s < DIM / 2; s += 2) {
            ulonglong2 v = xj[s >> 1];
            acc = ffma2(xi2[s], v.x, acc);
            acc = ffma2(xi2[s + 1], v.y, acc);
        }
        const float dot = pairsum(acc);
        const float d = fmaf(-2.f, dot, base_i + g_sq[j]);
        if (d < vals[KNN - 1] || (d == vals[KNN - 1] && j < idx[KNN - 1]))
            topk_insert_tie(vals, idx, d, j);
    }

    const float inv = g_sigma_inv;
    const float vi  = potential[row];
    float lap = 0.f;
#pragma unroll
    for (int t = 0; t < KNN; ++t) {
        float w = expf(-vals[t] * inv);
        lap += w * (potential[idx[t]] - vi);
    }
    out[row] = lap;
}

// ---------------------------------------------------------------------------
extern "C" void kernel_launch(void* const* d_in, const int* in_sizes, int n_in,
                              void* d_out, int out_size) {
    const float* coords    = (const float*)d_in[0];
    const float* potential = (const float*)d_in[1];
    float* out = (float*)d_out;

    cudaFuncSetAttribute(knn_mma_kernel,
                         cudaFuncAttributeMaxDynamicSharedMemorySize,
                         SMEM_BYTES);

    // knn_mma_kernel kept as the 4th launch -> it is the kernel ncu captures.
    hi_kernel<<<NPTS * DIM / 256, 256>>>(coords);     // 1
    sq_kernel<<<NPTS / 256, 256>>>(coords);           // 2
    colsum_kernel<<<DIM, 256>>>(coords);              // 3
    dim3 grid(NROWBLK, NSEG);
    knn_mma_kernel<<<grid, THREADS, SMEM_BYTES>>>();  // 4  <- profiled
    sigma_kernel<<<1, 256>>>();                       // 5
    rescore_lap_kernel<<<NPTS / 128, 128>>>(coords, potential, out);  // 6
}

// round 13
// speedup vs baseline: 3.6505x; 1.0177x over previous
#include <cuda_runtime.h>
#include <float.h>
#include <math.h>
#include <stdint.h>

// Problem constants
#define NPTS 12288
#define DIM 64
#define KNN 16
#define EPS 1e-5f
#define DIAG_BIAS 1e6f

// Tiling: 256 threads (8 warps x m16), BI=128 rows, BJ=64 cols per tile
#define THREADS 256
#define BI 128
#define BJ 64
#define NSEG 3
#define SEGJ (NPTS / NSEG)        // 4096
#define NTILES (SEGJ / BJ)        // 64
#define NROWBLK (NPTS / BI)       // 96
#define CPSEG 64                  // candidates emitted per (row, segment)
#define NCAND (NSEG * CPSEG)      // 192 candidates per row

// smem layout (floats). sj holds hi-only j-tiles, permuted k order: [col][64].
#define SJ_STRIDE 72
#define SJ_BUF (BJ * SJ_STRIDE)                      // 4608
#define SSQJ_OFF (2 * SJ_BUF)                        // 9216
#define SMEM_FLOATS (SSQJ_OFF + 2 * BJ)              // 9344
#define SMEM_BYTES (SMEM_FLOATS * 4)                 // 37376

// Scratch (no allocations -> device globals)
__device__ float  g_hi[NPTS * DIM];   // tf32-rounded coords, permuted k order
__device__ float  g_sq[NPTS];
__device__ float  g_colsum[DIM];
__device__ double g_part[48];
__device__ float  g_sigma_inv;
__device__ int    g_cand[NPTS * NCAND];

typedef unsigned long long u64;

__device__ __forceinline__ uint32_t sptr(const void* p) {
    return (uint32_t)__cvta_generic_to_shared(p);
}
__device__ __forceinline__ void cp_async16(uint32_t dst, const void* src) {
    asm volatile("cp.async.cg.shared.global [%0], [%1], 16;" :: "r"(dst), "l"(src));
}
__device__ __forceinline__ void cp_async4(uint32_t dst, const void* src) {
    asm volatile("cp.async.ca.shared.global [%0], [%1], 4;" :: "r"(dst), "l"(src));
}
#define CP_COMMIT() asm volatile("cp.async.commit_group;")
#define CP_WAIT0()  asm volatile("cp.async.wait_group 0;")

// packed fp32x2 fma (R2's exact-scoring instruction)
__device__ __forceinline__ u64 ffma2(u64 a, u64 b, u64 c) {
    u64 d;
    asm("fma.rn.f32x2 %0, %1, %2, %3;" : "=l"(d) : "l"(a), "l"(b), "l"(c));
    return d;
}
__device__ __forceinline__ float pairsum(u64 a) {
    float lo = __uint_as_float((unsigned)(a & 0xffffffffull));
    float hi = __uint_as_float((unsigned)(a >> 32));
    return lo + hi;
}

// m16n8k8 tf32 mma: D = A*B + D (row-major A, col-major B), fp32 accum
__device__ __forceinline__ void mma_tf32(float (&c)[4], const uint32_t* a,
                                         uint32_t b0, uint32_t b1) {
    asm volatile(
        "mma.sync.aligned.m16n8k8.row.col.f32.tf32.tf32.f32 "
        "{%0,%1,%2,%3}, {%4,%5,%6,%7}, {%8,%9}, {%0,%1,%2,%3};"
        : "+f"(c[0]), "+f"(c[1]), "+f"(c[2]), "+f"(c[3])
        : "r"(a[0]), "r"(a[1]), "r"(a[2]), "r"(a[3]), "r"(b0), "r"(b1));
}

// ---------------------------------------------------------------------------
// Prologue: tf32-round coords into g_hi with permuted k order.
// ---------------------------------------------------------------------------
__global__ void hi_kernel(const float* __restrict__ coords) {
    int i = blockIdx.x * 256 + threadIdx.x;   // 0 .. NPTS*DIM-1
    int row = i >> 6, k = i & 63;
    int kc = k >> 3, r = k & 7;
    int pos = kc * 8 + (r & 3) * 2 + (r >> 2);
    float x = coords[i];
    uint32_t h;
    asm("cvt.rna.tf32.f32 %0, %1;" : "=r"(h) : "f"(x));
    g_hi[row * DIM + pos] = __uint_as_float(h);
}

// ---------------------------------------------------------------------------
__global__ void sq_kernel(const float* __restrict__ coords) {
    int row = blockIdx.x * 256 + threadIdx.x;
    const float4* p = (const float4*)(coords + (size_t)row * DIM);
    float s = 0.f;
#pragma unroll
    for (int t = 0; t < DIM / 4; ++t) {
        float4 v = p[t];
        s += v.x * v.x + v.y * v.y + v.z * v.z + v.w * v.w;
    }
    g_sq[row] = s;
}

__global__ void colsum_kernel(const float* __restrict__ coords) {
    __shared__ float red[256];
    int d = blockIdx.x;
    float s = 0.f;
    for (int r = threadIdx.x; r < NPTS; r += 256)
        s += coords[(size_t)r * DIM + d];
    red[threadIdx.x] = s;
    __syncthreads();
    for (int off = 128; off > 0; off >>= 1) {
        if (threadIdx.x < off) red[threadIdx.x] += red[threadIdx.x + off];
        __syncthreads();
    }
    if (threadIdx.x == 0) g_colsum[d] = red[0];
}

// 48 partial double sums of g_sq (deterministic tree per block)
__global__ void sqsum_kernel() {
    __shared__ double red[256];
    double s = (double)g_sq[blockIdx.x * 256 + threadIdx.x];
    red[threadIdx.x] = s;
    __syncthreads();
    for (int off = 128; off > 0; off >>= 1) {
        if (threadIdx.x < off) red[threadIdx.x] += red[threadIdx.x + off];
        __syncthreads();
    }
    if (threadIdx.x == 0) g_part[blockIdx.x] = red[0];
}

__global__ void sigma_final_kernel() {
    if (threadIdx.x == 0) {
        double sumsq = 0.0;
        for (int i = 0; i < 48; ++i) sumsq += g_part[i];
        double nrm2 = 0.0;
        for (int d = 0; d < DIM; ++d) {
            double c = (double)g_colsum[d];
            nrm2 += c * c;
        }
        const double Nd = (double)NPTS;
        double total = 2.0 * Nd * sumsq - 2.0 * nrm2
                     + Nd * Nd * (double)EPS + Nd * (double)DIAG_BIAS;
        double sigma2 = total / (Nd * Nd);
        g_sigma_inv = (float)(1.0 / (sigma2 + (double)EPS));
    }
}

// lexicographic (value, index) sorted insert (exact selection semantics)
__device__ __forceinline__ void topk_insert_tie(float (&vals)[KNN],
                                                int (&idx)[KNN],
                                                float v, int id) {
#pragma unroll
    for (int t = 0; t < KNN; ++t) {
        bool lt = (v < vals[t]) || (v == vals[t] && id < idx[t]);
        if (lt) {
            float tv = vals[t]; vals[t] = v; v = tv;
            int   ti = idx[t];  idx[t]  = id; id = ti;
        }
    }
}

// register key-list insert, tail-biased: decay-phase inserts (k >= ks[7])
// walk only the last 8 slots. Caller guarantees k < ks[15].
__device__ __forceinline__ void key_insert(uint32_t (&ks)[16], uint32_t k) {
    if (k >= ks[7]) {
#pragma unroll
        for (int t = 8; t < 16; ++t) {
            uint32_t cur = ks[t];
            uint32_t lo = (k < cur) ? k : cur;
            uint32_t hi = (k < cur) ? cur : k;
            ks[t] = lo;
            k = hi;
        }
    } else {
#pragma unroll
        for (int t = 0; t < 16; ++t) {
            uint32_t cur = ks[t];
            uint32_t lo = (k < cur) ? k : cur;
            uint32_t hi = (k < cur) ? cur : k;
            ks[t] = lo;
            k = hi;
        }
    }
}

// ---------------------------------------------------------------------------
// Stage one 64-row hi-only j-tile (256B per row, direct copy of g_hi rows).
// ---------------------------------------------------------------------------
__device__ __forceinline__ void issue_jtile(int jbase, float* sjb,
                                            float* ssqjb, int tid) {
    int r = tid >> 2;        // 0..63 tile row
    int c4 = tid & 3;
    const float* src = g_hi + (size_t)(jbase + r) * DIM;
    float* dst = sjb + r * SJ_STRIDE;
#pragma unroll
    for (int m = 0; m < 4; ++m) {
        int ch = c4 + m * 4;  // 16B chunk 0..15
        cp_async16(sptr(dst + ch * 4), src + ch * 4);
    }
    if (tid < BJ) cp_async4(sptr(ssqjb + tid), &g_sq[jbase + tid]);
}

// ---------------------------------------------------------------------------
// Kernel B: single-tf32 tensor-core distance tiles + register-packed top-16.
// Diag hoisted to warp-uniform per-tile branch; fmin-gated insert path.
// ---------------------------------------------------------------------------
__global__ void __launch_bounds__(THREADS, 2)
knn_mma_kernel() {
    extern __shared__ float smem[];
    float* sj   = smem;
    float* ssqj = smem + SSQJ_OFF;

    const int tid = threadIdx.x;
    const int w = tid >> 5, l = tid & 31;
    const int g = l >> 2, t = l & 3;
    const int row0 = blockIdx.x * BI;
    const int jseg = blockIdx.y * SEGJ;
    const int rowA0 = row0 + w * 16 + g;
    const int rowA1 = rowA0 + 8;

    // warp-uniform: the single tile (if any) containing this warp's diagonal
    int diagTile = -1;
    if (rowA0 >= jseg && rowA0 < jseg + SEGJ) diagTile = (rowA0 - jseg) >> 6;

    uint32_t key0[16], key1[16];
#pragma unroll
    for (int k = 0; k < 16; ++k) { key0[k] = 0xFFFFFFFFu; key1[k] = 0xFFFFFFFFu; }

    // A fragments (persistent, hi only)
    uint32_t ah[32];
#pragma unroll
    for (int kc = 0; kc < 8; ++kc) {
        float2 p0 = *(const float2*)&g_hi[(size_t)rowA0 * DIM + kc * 8 + 2 * t];
        float2 p1 = *(const float2*)&g_hi[(size_t)rowA1 * DIM + kc * 8 + 2 * t];
        ah[kc * 4 + 0] = __float_as_uint(p0.x);
        ah[kc * 4 + 1] = __float_as_uint(p1.x);
        ah[kc * 4 + 2] = __float_as_uint(p0.y);
        ah[kc * 4 + 3] = __float_as_uint(p1.y);
    }
    const float sqi0e = g_sq[rowA0] + EPS;
    const float sqi1e = g_sq[rowA1] + EPS;

    issue_jtile(jseg, sj, ssqj, tid);
    CP_COMMIT();

    int buf = 0;
    for (int tile = 0; tile < NTILES; ++tile) {
        const int jbase = jseg + tile * BJ;
        CP_WAIT0();
        __syncthreads();

        if (tile + 1 < NTILES) {
            issue_jtile(jbase + BJ, sj + (buf ^ 1) * SJ_BUF,
                        ssqj + (buf ^ 1) * BJ, tid);
            CP_COMMIT();
        }

        const float* sjb = sj + buf * SJ_BUF;
        const float* ssqjb = ssqj + buf * BJ;
        const bool diagHere = (tile == diagTile);
#pragma unroll
        for (int nt2 = 0; nt2 < 4; ++nt2) {
            float c0[4] = {0.f, 0.f, 0.f, 0.f};
            float c1[4] = {0.f, 0.f, 0.f, 0.f};
            const float* b0p = sjb + (nt2 * 16 + g) * SJ_STRIDE + 2 * t;
            const float* b1p = sjb + (nt2 * 16 + 8 + g) * SJ_STRIDE + 2 * t;
#pragma unroll
            for (int kc = 0; kc < 8; ++kc) {
                float2 b0 = *(const float2*)(b0p + kc * 8);  // (k=t, k=t+4)
                float2 b1 = *(const float2*)(b1p + kc * 8);
                mma_tf32(c0, ah + kc * 4, __float_as_uint(b0.x), __float_as_uint(b0.y));
                mma_tf32(c1, ah + kc * 4, __float_as_uint(b1.x), __float_as_uint(b1.y));
            }
#pragma unroll
            for (int h = 0; h < 2; ++h) {
                const float* c = h ? c1 : c0;
                const int nt = nt2 * 2 + h;
                const int colb = nt * 8 + 2 * t;
                float2 sqj2 = *(const float2*)(ssqjb + colb);
                float d0 = fmaf(-2.f, c[0], sqi0e + sqj2.x);
                float d1 = fmaf(-2.f, c[1], sqi0e + sqj2.y);
                float d2 = fmaf(-2.f, c[2], sqi1e + sqj2.x);
                float d3 = fmaf(-2.f, c[3], sqi1e + sqj2.y);
                if (diagHere) {           // warp-uniform, one tile per segment
                    const int col0 = jbase + colb;
                    if (rowA0 == col0)     d0 += DIAG_BIAS;
                    if (rowA0 == col0 + 1) d1 += DIAG_BIAS;
                    if (rowA1 == col0)     d2 += DIAG_BIAS;
                    if (rowA1 == col0 + 1) d3 += DIAG_BIAS;
                }
                const uint32_t cin0 = (uint32_t)(tile * BJ + colb);
                uint32_t mm0 = __float_as_uint(fminf(d0, d1)) & 0xFFFFF000u;
                if (mm0 <= key0[15]) {
                    uint32_t k0 = (__float_as_uint(d0) & 0xFFFFF000u) | cin0;
                    uint32_t k1 = (__float_as_uint(d1) & 0xFFFFF000u) | (cin0 + 1);
                    if (k0 < key0[15]) key_insert(key0, k0);
                    if (k1 < key0[15]) key_insert(key0, k1);
                }
                uint32_t mm1 = __float_as_uint(fminf(d2, d3)) & 0xFFFFF000u;
                if (mm1 <= key1[15]) {
                    uint32_t k2 = (__float_as_uint(d2) & 0xFFFFF000u) | cin0;
                    uint32_t k3 = (__float_as_uint(d3) & 0xFFFFF000u) | (cin0 + 1);
                    if (k2 < key1[15]) key_insert(key1, k2);
                    if (k3 < key1[15]) key_insert(key1, k3);
                }
            }
        }
        buf ^= 1;
    }

    // ---- emit candidate indices (4 lanes x 16 per row-segment) ----
    {
        const size_t o0 = ((size_t)rowA0 * NSEG + blockIdx.y) * CPSEG + t * 16;
        const size_t o1 = ((size_t)rowA1 * NSEG + blockIdx.y) * CPSEG + t * 16;
#pragma unroll
        for (int k = 0; k < 16; ++k) {
            g_cand[o0 + k] = jseg + (int)(key0[k] & 0xFFFu);
            g_cand[o1 + k] = jseg + (int)(key1[k] & 0xFFFu);
        }
    }
}

// ---------------------------------------------------------------------------
// Kernel C: exact rescore, 4 threads per row (48 candidates each) with R2's
// EXACT arithmetic, then exact lexicographic merge in smem. Bit-identical
// selection to the serial version.
// ---------------------------------------------------------------------------
__global__ void __launch_bounds__(128)
rescore_lap_kernel(const float* __restrict__ coords,
                   const float* __restrict__ potential,
                   float* __restrict__ out) {
    __shared__ float sv[32 * 4 * KNN];
    __shared__ int   sx[32 * 4 * KNN];

    const int rloc = threadIdx.x >> 2;    // 0..31
    const int sub  = threadIdx.x & 3;
    const int row  = blockIdx.x * 32 + rloc;

    u64 xi2[DIM / 2];
    {
        const u64* p = (const u64*)(coords + (size_t)row * DIM);
#pragma unroll
        for (int s = 0; s < DIM / 2; ++s) xi2[s] = p[s];
    }
    const float base_i = g_sq[row] + EPS;

    float vals[KNN];
    int   idx[KNN];
#pragma unroll
    for (int t = 0; t < KNN; ++t) { vals[t] = FLT_MAX; idx[t] = 0x7fffffff; }

    const size_t cbase = (size_t)row * NCAND + sub * (NCAND / 4);
#pragma unroll 2
    for (int c = 0; c < NCAND / 4; ++c) {
        const int j = g_cand[cbase + c];
        const ulonglong2* xj = (const ulonglong2*)(coords + (size_t)j * DIM);
        u64 acc = 0ull;
#pragma unroll
        for (int s = 0; s < DIM / 2; s += 2) {
            ulonglong2 v = xj[s >> 1];
            acc = ffma2(xi2[s], v.x, acc);
            acc = ffma2(xi2[s + 1], v.y, acc);
        }
        const float dot = pairsum(acc);
        const float d = fmaf(-2.f, dot, base_i + g_sq[j]);
        if (d < vals[KNN - 1] || (d == vals[KNN - 1] && j < idx[KNN - 1]))
            topk_insert_tie(vals, idx, d, j);
    }

    // publish partial top-16 lists
    {
        float* pv = sv + (rloc * 4 + sub) * KNN;
        int*   px = sx + (rloc * 4 + sub) * KNN;
#pragma unroll
        for (int t = 0; t < KNN; ++t) { pv[t] = vals[t]; px[t] = idx[t]; }
    }
    __syncthreads();

    if (sub == 0) {
#pragma unroll
        for (int p = 1; p < 4; ++p) {
            const float* pv = sv + (rloc * 4 + p) * KNN;
            const int*   px = sx + (rloc * 4 + p) * KNN;
#pragma unroll
            for (int k = 0; k < KNN; ++k) {
                float v = pv[k];
                int   j = px[k];
                if (v < vals[KNN - 1] || (v == vals[KNN - 1] && j < idx[KNN - 1]))
                    topk_insert_tie(vals, idx, v, j);
            }
        }
        const float inv = g_sigma_inv;
        const float vi  = potential[row];
        float lap = 0.f;
#pragma unroll
        for (int t = 0; t < KNN; ++t) {
            float w = expf(-vals[t] * inv);
            lap += w * (potential[idx[t]] - vi);
        }
        out[row] = lap;
    }
}

// ---------------------------------------------------------------------------
extern "C" void kernel_launch(void* const* d_in, const int* in_sizes, int n_in,
                              void* d_out, int out_size) {
    const float* coords    = (const float*)d_in[0];
    const float* potential = (const float*)d_in[1];
    float* out = (float*)d_out;

    cudaFuncSetAttribute(knn_mma_kernel,
                         cudaFuncAttributeMaxDynamicSharedMemorySize,
                         SMEM_BYTES);

    // knn_mma_kernel kept as the 4th launch -> it is the kernel ncu captures.
    hi_kernel<<<NPTS * DIM / 256, 256>>>(coords);     // 1
    sq_kernel<<<NPTS / 256, 256>>>(coords);           // 2
    colsum_kernel<<<DIM, 256>>>(coords);              // 3
    dim3 grid(NROWBLK, NSEG);
    knn_mma_kernel<<<grid, THREADS, SMEM_BYTES>>>();  // 4  <- profiled
    sqsum_kernel<<<48, 256>>>();                      // 5
    sigma_final_kernel<<<1, 32>>>();                  // 6
    rescore_lap_kernel<<<NPTS / 32, 128>>>(coords, potential, out);  // 7
}